// round 1
// baseline (speedup 1.0000x reference)
#include <cuda_runtime.h>
#include <math.h>

#define NROWS 8192
#define DDIM  256
#define INV_TAU 10.0f
#define EPSV 1e-8f

#define BM 128
#define BK 32

// Scratch (device globals only -- no allocation anywhere)
__device__ float g_xn[NROWS * DDIM];          // normalized rows, 8 MB
__device__ float g_part[64 * NROWS];          // per-(column-block) partial row sums, 2 MB
__device__ float g_blk[8];                    // per-block log sums

// ---------------------------------------------------------------------------
// Kernel 1: L2-normalize each row. One warp per row.
// ---------------------------------------------------------------------------
__global__ void nk_normalize(const float* __restrict__ x) {
    int row  = (blockIdx.x * blockDim.x + threadIdx.x) >> 5;
    int lane = threadIdx.x & 31;
    if (row >= NROWS) return;
    const float4* xr = (const float4*)(x + (size_t)row * DDIM);
    float4 v0 = xr[lane];
    float4 v1 = xr[lane + 32];
    float s = v0.x*v0.x + v0.y*v0.y + v0.z*v0.z + v0.w*v0.w
            + v1.x*v1.x + v1.y*v1.y + v1.z*v1.z + v1.w*v1.w;
    #pragma unroll
    for (int o = 16; o > 0; o >>= 1) s += __shfl_xor_sync(0xffffffffu, s, o);
    float inv = 1.0f / fmaxf(sqrtf(s), 1e-12f);
    v0.x *= inv; v0.y *= inv; v0.z *= inv; v0.w *= inv;
    v1.x *= inv; v1.y *= inv; v1.z *= inv; v1.w *= inv;
    float4* o4 = (float4*)(g_xn + (size_t)row * DDIM);
    o4[lane]      = v0;
    o4[lane + 32] = v1;
}

// ---------------------------------------------------------------------------
// Kernel 2: fused 128x128-tile SGEMM (xn @ xn^T) * INV_TAU -> exp -> row sums.
// 256 threads, 8x8 micro-tile per thread with 4+4 split for conflict-light LDS.
// Writes per-tile partial row sums to g_part[bn][row] -- no atomics.
// ---------------------------------------------------------------------------
__global__ __launch_bounds__(256) void nk_gemm(void) {
    __shared__ float As[BK][BM];
    __shared__ float Bs[BK][BM];

    const int m0  = blockIdx.y * BM;
    const int n0  = blockIdx.x * BM;
    const int tid = threadIdx.x;
    const int tx  = tid & 15;
    const int ty  = tid >> 4;
    const int lrow = tid >> 3;         // 0..31
    const int lk   = (tid & 7) << 2;   // 0,4,...,28

    float acc[8][8];
    #pragma unroll
    for (int i = 0; i < 8; i++)
        #pragma unroll
        for (int j = 0; j < 8; j++)
            acc[i][j] = 0.0f;

    for (int k0 = 0; k0 < DDIM; k0 += BK) {
        #pragma unroll
        for (int p = 0; p < 4; p++) {
            int r = lrow + p * 32;
            float4 va = *(const float4*)(g_xn + (size_t)(m0 + r) * DDIM + k0 + lk);
            As[lk+0][r] = va.x; As[lk+1][r] = va.y; As[lk+2][r] = va.z; As[lk+3][r] = va.w;
            float4 vb = *(const float4*)(g_xn + (size_t)(n0 + r) * DDIM + k0 + lk);
            Bs[lk+0][r] = vb.x; Bs[lk+1][r] = vb.y; Bs[lk+2][r] = vb.z; Bs[lk+3][r] = vb.w;
        }
        __syncthreads();

        #pragma unroll 8
        for (int k = 0; k < BK; k++) {
            float a[8], b[8];
            *(float4*)&a[0] = *(const float4*)&As[k][ty * 4];
            *(float4*)&a[4] = *(const float4*)&As[k][64 + ty * 4];
            *(float4*)&b[0] = *(const float4*)&Bs[k][tx * 4];
            *(float4*)&b[4] = *(const float4*)&Bs[k][64 + tx * 4];
            #pragma unroll
            for (int i = 0; i < 8; i++)
                #pragma unroll
                for (int j = 0; j < 8; j++)
                    acc[i][j] = fmaf(a[i], b[j], acc[i][j]);
        }
        __syncthreads();
    }

    // Epilogue: exp, zero the diagonal, partial row sums over this 128-col tile.
    float rs[8];
    #pragma unroll
    for (int i = 0; i < 8; i++) {
        int lr = (i < 4) ? (ty * 4 + i) : (64 + ty * 4 + i - 4);
        int gr = m0 + lr;
        float s = 0.0f;
        #pragma unroll
        for (int j = 0; j < 8; j++) {
            int gc = n0 + ((j < 4) ? (tx * 4 + j) : (64 + tx * 4 + j - 4));
            float e = __expf(acc[i][j] * INV_TAU);
            s += (gr == gc) ? 0.0f : e;
        }
        rs[i] = s;
    }

    __syncthreads();                 // done with smem tiles; reuse As as scratch
    float* red = &As[0][0];          // 128 rows x 16 tx = 2048 floats (fits in As)
    #pragma unroll
    for (int i = 0; i < 8; i++) {
        int lr = (i < 4) ? (ty * 4 + i) : (64 + ty * 4 + i - 4);
        red[lr * 16 + tx] = rs[i];
    }
    __syncthreads();

    if (tid < 128) {
        float s = 0.0f;
        #pragma unroll
        for (int j = 0; j < 16; j++) s += red[tid * 16 + j];
        g_part[(size_t)blockIdx.x * NROWS + (m0 + tid)] = s;   // coalesced
    }
}

// ---------------------------------------------------------------------------
// Kernel 3: per-row sum of 64 partials -> log -> block reduction (deterministic).
// ---------------------------------------------------------------------------
__global__ void nk_rowlog(void) {
    __shared__ float sm[1024];
    int tid = threadIdx.x;
    int r = blockIdx.x * 1024 + tid;
    float s = 0.0f;
    #pragma unroll
    for (int j = 0; j < 64; j++) s += g_part[(size_t)j * NROWS + r];  // coalesced
    sm[tid] = logf(s * (1.0f / (float)(NROWS - 1)) + EPSV);
    __syncthreads();
    for (int o = 512; o > 0; o >>= 1) {
        if (tid < o) sm[tid] += sm[tid + o];
        __syncthreads();
    }
    if (tid == 0) g_blk[blockIdx.x] = sm[0];
}

__global__ void nk_final(float* __restrict__ out) {
    if (threadIdx.x == 0) {
        float s = 0.0f;
        #pragma unroll
        for (int j = 0; j < 8; j++) s += g_blk[j];
        out[0] = s / (float)NROWS;
    }
}

// ---------------------------------------------------------------------------
extern "C" void kernel_launch(void* const* d_in, const int* in_sizes, int n_in,
                              void* d_out, int out_size) {
    (void)in_sizes; (void)n_in; (void)out_size;
    const float* x = (const float*)d_in[0];
    float* out = (float*)d_out;

    nk_normalize<<<NROWS / 8, 256>>>(x);
    dim3 grid(NROWS / BM, NROWS / BM);
    nk_gemm<<<grid, 256>>>();
    nk_rowlog<<<NROWS / 1024, 1024>>>();
    nk_final<<<1, 32>>>(out);
}

// round 3
// speedup vs baseline: 2.6225x; 2.6225x over previous
#include <cuda_runtime.h>
#include <cuda_bf16.h>
#include <math.h>
#include <stdint.h>

#define NROWS 8192
#define DDIM  256
#define INV_TAU 10.0f
#define EPSV 1e-8f

#define BM 128
#define BK 32
#define NCHUNK (DDIM / BK)   // 8

// ---------------- device scratch (globals only; no allocation) --------------
__device__ __nv_bfloat16 g_xh[NROWS * DDIM];   // hi bf16 of normalized rows (4 MB)
__device__ __nv_bfloat16 g_xl[NROWS * DDIM];   // lo bf16 residual          (4 MB)
__device__ float g_part[(NROWS / BM) * NROWS]; // per column-block partial row sums (2 MB)
__device__ float g_blk[8];

// ---------------- helpers ----------------------------------------------------
__device__ __forceinline__ uint32_t smem_u32(const void* p) {
    uint32_t a;
    asm("{ .reg .u64 t; cvta.to.shared.u64 t, %1; cvt.u32.u64 %0, t; }" : "=r"(a) : "l"(p));
    return a;
}

#define CP16(dst, src) \
    asm volatile("cp.async.cg.shared.global [%0], [%1], 16;" :: "r"(dst), "l"(src))
#define CP_COMMIT() asm volatile("cp.async.commit_group;")
#define CP_WAIT(n)  asm volatile("cp.async.wait_group %0;" :: "n"(n))

__device__ __forceinline__ void ldsm_x4(uint32_t* r, uint32_t addr) {
    asm volatile("ldmatrix.sync.aligned.m8n8.x4.shared.b16 {%0,%1,%2,%3}, [%4];"
                 : "=r"(r[0]), "=r"(r[1]), "=r"(r[2]), "=r"(r[3]) : "r"(addr));
}

__device__ __forceinline__ void mma16816(float* c, const uint32_t* a, const uint32_t* b) {
    asm volatile(
        "mma.sync.aligned.m16n8k16.row.col.f32.bf16.bf16.f32 "
        "{%0,%1,%2,%3}, {%4,%5,%6,%7}, {%8,%9}, {%0,%1,%2,%3};"
        : "+f"(c[0]), "+f"(c[1]), "+f"(c[2]), "+f"(c[3])
        : "r"(a[0]), "r"(a[1]), "r"(a[2]), "r"(a[3]), "r"(b[0]), "r"(b[1]));
}

// swizzled byte offset within a [128 rows x 64B] tile
__device__ __forceinline__ uint32_t swz(int r, int c16) {
    return (uint32_t)(r * 64 + ((c16 ^ ((r >> 1) & 3)) << 4));
}

// SMEM stage layout
#define T_AH 0
#define T_AL 8192
#define T_BH 16384
#define T_BL 24576
#define STAGE 32768
#define SM_TOTAL (2 * STAGE)   // 64 KB

// ---------------------------------------------------------------------------
// Kernel 1: L2-normalize rows, split into bf16 hi + lo. One warp per row.
// ---------------------------------------------------------------------------
__global__ void nk_normalize(const float* __restrict__ x) {
    int row  = (blockIdx.x * blockDim.x + threadIdx.x) >> 5;
    int lane = threadIdx.x & 31;
    if (row >= NROWS) return;
    const float4* xr = (const float4*)(x + (size_t)row * DDIM);
    float4 v0 = xr[lane * 2];
    float4 v1 = xr[lane * 2 + 1];
    float s = v0.x*v0.x + v0.y*v0.y + v0.z*v0.z + v0.w*v0.w
            + v1.x*v1.x + v1.y*v1.y + v1.z*v1.z + v1.w*v1.w;
    #pragma unroll
    for (int o = 16; o > 0; o >>= 1) s += __shfl_xor_sync(0xffffffffu, s, o);
    float inv = 1.0f / fmaxf(sqrtf(s), 1e-12f);

    float e[8] = {v0.x*inv, v0.y*inv, v0.z*inv, v0.w*inv,
                  v1.x*inv, v1.y*inv, v1.z*inv, v1.w*inv};
    union { __nv_bfloat16 h[8]; float4 v; } uh, ul;
    #pragma unroll
    for (int i = 0; i < 8; i++) {
        __nv_bfloat16 hb = __float2bfloat16(e[i]);
        uh.h[i] = hb;
        ul.h[i] = __float2bfloat16(e[i] - __bfloat162float(hb));
    }
    ((float4*)(g_xh + (size_t)row * DDIM))[lane] = uh.v;
    ((float4*)(g_xl + (size_t)row * DDIM))[lane] = ul.v;
}

// ---------------------------------------------------------------------------
// Kernel 2: bf16 hi/lo 3-pass GEMM via mma.sync + fused exp/rowsum epilogue.
// 256 threads, 8 warps (4 m x 2 n), warp tile 32x64, BK=32, 2-stage cp.async.
// ---------------------------------------------------------------------------
__device__ __forceinline__ void load_stage(uint32_t st, int m0, int n0, int k0, int tid) {
    const char* ah = (const char*)g_xh;
    const char* al = (const char*)g_xl;
    #pragma unroll
    for (int i = 0; i < 2; i++) {
        int idx = tid + i * 256;
        int r   = idx >> 2;          // 0..127
        int c16 = idx & 3;           // 16B chunk
        size_t goffA = (size_t)(m0 + r) * (DDIM * 2) + (size_t)k0 * 2 + c16 * 16;
        size_t goffB = (size_t)(n0 + r) * (DDIM * 2) + (size_t)k0 * 2 + c16 * 16;
        uint32_t so = swz(r, c16);
        CP16(st + T_AH + so, ah + goffA);
        CP16(st + T_AL + so, al + goffA);
        CP16(st + T_BH + so, ah + goffB);
        CP16(st + T_BL + so, al + goffB);
    }
}

__global__ __launch_bounds__(256) void nk_gemm_mma(void) {
    extern __shared__ char smem[];
    const uint32_t sb = smem_u32(smem);
    const int tid  = threadIdx.x;
    const int lane = tid & 31;
    const int wid  = tid >> 5;
    const int wm   = wid & 3;       // warp row   (0..3) -> rows wm*32
    const int wn   = wid >> 2;      // warp col   (0..1) -> cols wn*64
    const int m0 = blockIdx.y * BM;
    const int n0 = blockIdx.x * BM;

    float acc[2][8][4];
    #pragma unroll
    for (int mi = 0; mi < 2; mi++)
        #pragma unroll
        for (int ni = 0; ni < 8; ni++)
            #pragma unroll
            for (int e = 0; e < 4; e++) acc[mi][ni][e] = 0.0f;

    // ldmatrix per-lane source coordinates
    const int a_row = lane & 15;            // row within 16-row A tile
    const int a_kk  = lane >> 4;            // 0/1 : 16B chunk within k16
    const int b_g   = lane >> 3;            // 0..3
    const int b_row = ((b_g >> 1) << 3) + (lane & 7);  // n within 16-col B tile
    const int b_kk  = b_g & 1;

    load_stage(sb, m0, n0, 0, tid);
    CP_COMMIT();

    for (int ch = 0; ch < NCHUNK; ch++) {
        if (ch + 1 < NCHUNK) {
            load_stage(sb + ((ch + 1) & 1) * STAGE, m0, n0, (ch + 1) * BK, tid);
            CP_COMMIT();
            CP_WAIT(1);
        } else {
            CP_WAIT(0);
        }
        __syncthreads();

        const uint32_t st = sb + (ch & 1) * STAGE;
        #pragma unroll
        for (int pass = 0; pass < 3; pass++) {
            const uint32_t At = st + (pass == 2 ? T_AL : T_AH);
            const uint32_t Bt = st + (pass == 1 ? T_BL : T_BH);
            #pragma unroll
            for (int s = 0; s < 2; s++) {         // two k16 steps per BK=32
                uint32_t afr[2][4];
                #pragma unroll
                for (int mi = 0; mi < 2; mi++) {
                    int r = wm * 32 + mi * 16 + a_row;
                    ldsm_x4(afr[mi], At + swz(r, s * 2 + a_kk));
                }
                uint32_t bfr[4][4];
                #pragma unroll
                for (int nq = 0; nq < 4; nq++) {
                    int n = wn * 64 + nq * 16 + b_row;
                    ldsm_x4(bfr[nq], Bt + swz(n, s * 2 + b_kk));
                }
                #pragma unroll
                for (int mi = 0; mi < 2; mi++)
                    #pragma unroll
                    for (int ni = 0; ni < 8; ni++)
                        mma16816(acc[mi][ni], afr[mi], &bfr[ni >> 1][(ni & 1) * 2]);
            }
        }
        __syncthreads();
    }

    // Epilogue: exp, zero diag, row sums over the warp's 64-col span.
    const bool diag = (blockIdx.x == blockIdx.y);
    float* red = (float*)smem;               // [128][2] floats, reuse stage smem
    #pragma unroll
    for (int mi = 0; mi < 2; mi++) {
        #pragma unroll
        for (int half = 0; half < 2; half++) {
            int rloc = wm * 32 + mi * 16 + (lane >> 2) + half * 8;
            float s = 0.0f;
            #pragma unroll
            for (int ni = 0; ni < 8; ni++) {
                #pragma unroll
                for (int c = 0; c < 2; c++) {
                    int cloc = wn * 64 + ni * 8 + (lane & 3) * 2 + c;
                    float v = __expf(acc[mi][ni][half * 2 + c] * INV_TAU);
                    s += (diag && rloc == cloc) ? 0.0f : v;
                }
            }
            s += __shfl_xor_sync(0xffffffffu, s, 1);
            s += __shfl_xor_sync(0xffffffffu, s, 2);
            if ((lane & 3) == 0) red[rloc * 2 + wn] = s;
        }
    }
    __syncthreads();
    if (tid < 128)
        g_part[(size_t)blockIdx.x * NROWS + (m0 + tid)] = red[tid * 2] + red[tid * 2 + 1];
}

// ---------------------------------------------------------------------------
// Kernel 3: per-row sum of 64 partials -> log -> block reduce (deterministic).
// ---------------------------------------------------------------------------
__global__ void nk_rowlog(void) {
    __shared__ float sm[1024];
    int tid = threadIdx.x;
    int r = blockIdx.x * 1024 + tid;
    float s = 0.0f;
    #pragma unroll
    for (int j = 0; j < NROWS / BM; j++) s += g_part[(size_t)j * NROWS + r];
    sm[tid] = logf(s * (1.0f / (float)(NROWS - 1)) + EPSV);
    __syncthreads();
    for (int o = 512; o > 0; o >>= 1) {
        if (tid < o) sm[tid] += sm[tid + o];
        __syncthreads();
    }
    if (tid == 0) g_blk[blockIdx.x] = sm[0];
}

__global__ void nk_final(float* __restrict__ out) {
    if (threadIdx.x == 0) {
        float s = 0.0f;
        #pragma unroll
        for (int j = 0; j < 8; j++) s += g_blk[j];
        out[0] = s / (float)NROWS;
    }
}

// ---------------------------------------------------------------------------
extern "C" void kernel_launch(void* const* d_in, const int* in_sizes, int n_in,
                              void* d_out, int out_size) {
    (void)in_sizes; (void)n_in; (void)out_size;
    const float* x = (const float*)d_in[0];
    float* out = (float*)d_out;

    cudaFuncSetAttribute(nk_gemm_mma, cudaFuncAttributeMaxDynamicSharedMemorySize, SM_TOTAL);

    nk_normalize<<<NROWS / 8, 256>>>(x);
    dim3 grid(NROWS / BM, NROWS / BM);
    nk_gemm_mma<<<grid, 256, SM_TOTAL>>>();
    nk_rowlog<<<NROWS / 1024, 1024>>>();
    nk_final<<<1, 32>>>(out);
}

// round 4
// speedup vs baseline: 4.2497x; 1.6205x over previous
#include <cuda_runtime.h>
#include <cuda_bf16.h>
#include <math.h>
#include <stdint.h>

#define NROWS 8192
#define DDIM  256
#define INV_TAU 10.0f
#define EPSV 1e-8f

#define BM 128
#define BK 32
#define NCHUNK (DDIM / BK)   // 8
#define NBLK   (NROWS / BM)  // 64
#define NTRI   (NBLK * (NBLK + 1) / 2)  // 2080

// ---------------- device scratch (globals only; no allocation) --------------
__device__ __nv_bfloat16 g_xh[NROWS * DDIM];   // hi bf16 of normalized rows (4 MB)
__device__ __nv_bfloat16 g_xl[NROWS * DDIM];   // lo bf16 residual          (4 MB)
__device__ float g_part[NBLK * NROWS];         // [col-block][row] partial sums (2 MB)
__device__ float g_blk[8];

// ---------------- helpers ----------------------------------------------------
__device__ __forceinline__ uint32_t smem_u32(const void* p) {
    uint32_t a;
    asm("{ .reg .u64 t; cvta.to.shared.u64 t, %1; cvt.u32.u64 %0, t; }" : "=r"(a) : "l"(p));
    return a;
}

#define CP16(dst, src) \
    asm volatile("cp.async.cg.shared.global [%0], [%1], 16;" :: "r"(dst), "l"(src))
#define CP_COMMIT() asm volatile("cp.async.commit_group;")
#define CP_WAIT(n)  asm volatile("cp.async.wait_group %0;" :: "n"(n))

__device__ __forceinline__ void ldsm_x4(uint32_t* r, uint32_t addr) {
    asm volatile("ldmatrix.sync.aligned.m8n8.x4.shared.b16 {%0,%1,%2,%3}, [%4];"
                 : "=r"(r[0]), "=r"(r[1]), "=r"(r[2]), "=r"(r[3]) : "r"(addr));
}

__device__ __forceinline__ void mma16816(float* c, const uint32_t* a, const uint32_t* b) {
    asm volatile(
        "mma.sync.aligned.m16n8k16.row.col.f32.bf16.bf16.f32 "
        "{%0,%1,%2,%3}, {%4,%5,%6,%7}, {%8,%9}, {%0,%1,%2,%3};"
        : "+f"(c[0]), "+f"(c[1]), "+f"(c[2]), "+f"(c[3])
        : "r"(a[0]), "r"(a[1]), "r"(a[2]), "r"(a[3]), "r"(b[0]), "r"(b[1]));
}

// swizzled byte offset within a [128 rows x 64B] tile
__device__ __forceinline__ uint32_t swz(int r, int c16) {
    return (uint32_t)(r * 64 + ((c16 ^ ((r >> 1) & 3)) << 4));
}

// SMEM stage layout
#define T_AH 0
#define T_AL 8192
#define T_BH 16384
#define T_BL 24576
#define STAGE 32768
#define SM_TOTAL (2 * STAGE)   // 64 KB

// ---------------------------------------------------------------------------
// Kernel 1: L2-normalize rows, split into bf16 hi + lo. One warp per row.
// ---------------------------------------------------------------------------
__global__ void nk_normalize(const float* __restrict__ x) {
    int row  = (blockIdx.x * blockDim.x + threadIdx.x) >> 5;
    int lane = threadIdx.x & 31;
    if (row >= NROWS) return;
    const float4* xr = (const float4*)(x + (size_t)row * DDIM);
    float4 v0 = xr[lane * 2];
    float4 v1 = xr[lane * 2 + 1];
    float s = v0.x*v0.x + v0.y*v0.y + v0.z*v0.z + v0.w*v0.w
            + v1.x*v1.x + v1.y*v1.y + v1.z*v1.z + v1.w*v1.w;
    #pragma unroll
    for (int o = 16; o > 0; o >>= 1) s += __shfl_xor_sync(0xffffffffu, s, o);
    float inv = 1.0f / fmaxf(sqrtf(s), 1e-12f);

    float e[8] = {v0.x*inv, v0.y*inv, v0.z*inv, v0.w*inv,
                  v1.x*inv, v1.y*inv, v1.z*inv, v1.w*inv};
    union { __nv_bfloat16 h[8]; float4 v; } uh, ul;
    #pragma unroll
    for (int i = 0; i < 8; i++) {
        __nv_bfloat16 hb = __float2bfloat16(e[i]);
        uh.h[i] = hb;
        ul.h[i] = __float2bfloat16(e[i] - __bfloat162float(hb));
    }
    ((float4*)(g_xh + (size_t)row * DDIM))[lane] = uh.v;
    ((float4*)(g_xl + (size_t)row * DDIM))[lane] = ul.v;
}

// ---------------------------------------------------------------------------
// Kernel 2: upper-triangular bf16 hi/lo 3-pass GEMM via mma.sync.
// Each off-diagonal tile produces BOTH row sums (for block-row bm) and
// column sums (for block-row bn, by symmetry). Diagonal tiles: row sums only.
// ---------------------------------------------------------------------------
__device__ __forceinline__ void load_stage(uint32_t st, int m0, int n0, int k0, int tid) {
    const char* ah = (const char*)g_xh;
    const char* al = (const char*)g_xl;
    #pragma unroll
    for (int i = 0; i < 2; i++) {
        int idx = tid + i * 256;
        int r   = idx >> 2;          // 0..127
        int c16 = idx & 3;           // 16B chunk
        size_t goffA = (size_t)(m0 + r) * (DDIM * 2) + (size_t)k0 * 2 + c16 * 16;
        size_t goffB = (size_t)(n0 + r) * (DDIM * 2) + (size_t)k0 * 2 + c16 * 16;
        uint32_t so = swz(r, c16);
        CP16(st + T_AH + so, ah + goffA);
        CP16(st + T_AL + so, al + goffA);
        CP16(st + T_BH + so, ah + goffB);
        CP16(st + T_BL + so, al + goffB);
    }
}

__global__ __launch_bounds__(256) void nk_gemm_mma(void) {
    extern __shared__ char smem[];
    const uint32_t sb = smem_u32(smem);
    const int tid  = threadIdx.x;
    const int lane = tid & 31;
    const int wid  = tid >> 5;
    const int wm   = wid & 3;       // warp row (0..3) -> rows wm*32
    const int wn   = wid >> 2;      // warp col (0..1) -> cols wn*64

    // Decode upper-triangular (bm <= bn) from linear block id.
    int t = blockIdx.x;
    int bm = (int)(64.5 - sqrt(64.5 * 64.5 - 2.0 * (double)t));
    // f(bm) = number of tiles before block-row bm
    #define FTRI(i) ((i) * NBLK - (i) * ((i) - 1) / 2)
    while (FTRI(bm + 1) <= t) bm++;
    while (FTRI(bm) > t) bm--;
    const int bn = bm + (t - FTRI(bm));
    const int m0 = bm * BM;
    const int n0 = bn * BM;
    const bool diag = (bm == bn);

    float acc[2][8][4];
    #pragma unroll
    for (int mi = 0; mi < 2; mi++)
        #pragma unroll
        for (int ni = 0; ni < 8; ni++)
            #pragma unroll
            for (int e = 0; e < 4; e++) acc[mi][ni][e] = 0.0f;

    const int a_row = lane & 15;
    const int a_kk  = lane >> 4;
    const int b_g   = lane >> 3;
    const int b_row = ((b_g >> 1) << 3) + (lane & 7);
    const int b_kk  = b_g & 1;

    load_stage(sb, m0, n0, 0, tid);
    CP_COMMIT();

    for (int ch = 0; ch < NCHUNK; ch++) {
        if (ch + 1 < NCHUNK) {
            load_stage(sb + ((ch + 1) & 1) * STAGE, m0, n0, (ch + 1) * BK, tid);
            CP_COMMIT();
            CP_WAIT(1);
        } else {
            CP_WAIT(0);
        }
        __syncthreads();

        const uint32_t st = sb + (ch & 1) * STAGE;
        #pragma unroll
        for (int pass = 0; pass < 3; pass++) {
            const uint32_t At = st + (pass == 2 ? T_AL : T_AH);
            const uint32_t Bt = st + (pass == 1 ? T_BL : T_BH);
            #pragma unroll
            for (int s = 0; s < 2; s++) {
                uint32_t afr[2][4];
                #pragma unroll
                for (int mi = 0; mi < 2; mi++) {
                    int r = wm * 32 + mi * 16 + a_row;
                    ldsm_x4(afr[mi], At + swz(r, s * 2 + a_kk));
                }
                uint32_t bfr[4][4];
                #pragma unroll
                for (int nq = 0; nq < 4; nq++) {
                    int n = wn * 64 + nq * 16 + b_row;
                    ldsm_x4(bfr[nq], Bt + swz(n, s * 2 + b_kk));
                }
                #pragma unroll
                for (int mi = 0; mi < 2; mi++)
                    #pragma unroll
                    for (int ni = 0; ni < 8; ni++)
                        mma16816(acc[mi][ni], afr[mi], &bfr[ni >> 1][(ni & 1) * 2]);
            }
        }
        __syncthreads();
    }

    // ---- Epilogue: exp once; accumulate row sums AND column sums ----------
    float rowacc[2][2];                      // [mi][half]
    float colacc[8][2];                      // [ni][c]
    #pragma unroll
    for (int mi = 0; mi < 2; mi++) { rowacc[mi][0] = 0.0f; rowacc[mi][1] = 0.0f; }
    #pragma unroll
    for (int ni = 0; ni < 8; ni++) { colacc[ni][0] = 0.0f; colacc[ni][1] = 0.0f; }

    #pragma unroll
    for (int mi = 0; mi < 2; mi++) {
        #pragma unroll
        for (int ni = 0; ni < 8; ni++) {
            #pragma unroll
            for (int half = 0; half < 2; half++) {
                #pragma unroll
                for (int c = 0; c < 2; c++) {
                    int rloc = wm * 32 + mi * 16 + (lane >> 2) + half * 8;
                    int cloc = wn * 64 + ni * 8 + (lane & 3) * 2 + c;
                    float v = __expf(acc[mi][ni][half * 2 + c] * INV_TAU);
                    if (diag && rloc == cloc) v = 0.0f;
                    rowacc[mi][half] += v;
                    colacc[ni][c]    += v;
                }
            }
        }
    }

    float* red    = (float*)smem;            // [128][2]   row partials (1 KB)
    float* colred = (float*)smem + 256;      // [8][64]    col partials (2 KB)

    // Row sums: reduce over lane&3 (shfl 1,2); lane%4==0 holds result.
    #pragma unroll
    for (int mi = 0; mi < 2; mi++)
        #pragma unroll
        for (int half = 0; half < 2; half++) {
            float s = rowacc[mi][half];
            s += __shfl_xor_sync(0xffffffffu, s, 1);
            s += __shfl_xor_sync(0xffffffffu, s, 2);
            if ((lane & 3) == 0) {
                int rloc = wm * 32 + mi * 16 + (lane >> 2) + half * 8;
                red[rloc * 2 + wn] = s;
            }
        }

    // Column sums: reduce over lane>>2 (shfl 4,8,16); lanes 0..3 write.
    if (!diag) {
        #pragma unroll
        for (int ni = 0; ni < 8; ni++)
            #pragma unroll
            for (int c = 0; c < 2; c++) {
                float s = colacc[ni][c];
                s += __shfl_xor_sync(0xffffffffu, s, 4);
                s += __shfl_xor_sync(0xffffffffu, s, 8);
                s += __shfl_xor_sync(0xffffffffu, s, 16);
                if (lane < 4) {
                    int cloc = wn * 64 + ni * 8 + lane * 2 + c;
                    colred[wid * 64 + (cloc & 63)] = s;
                }
            }
    }
    __syncthreads();

    if (tid < 128) {
        g_part[(size_t)bn * NROWS + (m0 + tid)] = red[tid * 2] + red[tid * 2 + 1];
        if (!diag) {
            int w = tid >> 6;                // wn of this column
            int cc = tid & 63;
            float cs = colred[(w * 4 + 0) * 64 + cc] + colred[(w * 4 + 1) * 64 + cc]
                     + colred[(w * 4 + 2) * 64 + cc] + colred[(w * 4 + 3) * 64 + cc];
            g_part[(size_t)bm * NROWS + (n0 + tid)] = cs;
        }
    }
}

// ---------------------------------------------------------------------------
// Kernel 3: per-row sum of 64 partials -> log -> block reduce (deterministic).
// ---------------------------------------------------------------------------
__global__ void nk_rowlog(void) {
    __shared__ float sm[1024];
    int tid = threadIdx.x;
    int r = blockIdx.x * 1024 + tid;
    float s = 0.0f;
    #pragma unroll
    for (int j = 0; j < NBLK; j++) s += g_part[(size_t)j * NROWS + r];
    sm[tid] = logf(s * (1.0f / (float)(NROWS - 1)) + EPSV);
    __syncthreads();
    for (int o = 512; o > 0; o >>= 1) {
        if (tid < o) sm[tid] += sm[tid + o];
        __syncthreads();
    }
    if (tid == 0) g_blk[blockIdx.x] = sm[0];
}

__global__ void nk_final(float* __restrict__ out) {
    if (threadIdx.x == 0) {
        float s = 0.0f;
        #pragma unroll
        for (int j = 0; j < 8; j++) s += g_blk[j];
        out[0] = s / (float)NROWS;
    }
}

// ---------------------------------------------------------------------------
extern "C" void kernel_launch(void* const* d_in, const int* in_sizes, int n_in,
                              void* d_out, int out_size) {
    (void)in_sizes; (void)n_in; (void)out_size;
    const float* x = (const float*)d_in[0];
    float* out = (float*)d_out;

    cudaFuncSetAttribute(nk_gemm_mma, cudaFuncAttributeMaxDynamicSharedMemorySize, SM_TOTAL);

    nk_normalize<<<NROWS / 8, 256>>>(x);
    nk_gemm_mma<<<NTRI, 256, SM_TOTAL>>>();
    nk_rowlog<<<NROWS / 1024, 1024>>>();
    nk_final<<<1, 32>>>(out);
}